// round 16
// baseline (speedup 1.0000x reference)
#include <cuda_runtime.h>
#include <cuda_fp16.h>
#include <cstdint>

// Problem constants (HT2SPHERE: B=4, C=64, H=128, W=128, S=16384, V=1e6)
#define HW    16384     // H*W
#define BC    256       // B*C
#define SPH   16384     // sphere_size
#define CAP   512       // fixed bucket capacity per sphere (Poisson(61); P(overflow)~0)
#define CAPSH 9         // log2(CAP)
#define SPB   16        // spheres per block in sphere_accum_k (16 warps)
#define TIN   64        // transpose tile edge

// ---------------- device scratch (allocation-free rule: __device__ globals) ----
// NOTE: only referenced from device code (host-side symbol decay = ATS shadow bug).
// g_cursor: zero at module load; sphere_accum_k re-zeroes each entry after use,
// so EVERY call (correctness, capture, replay) starts from a zeroed cursor.
__device__ __align__(16) __half  g_xTh[(size_t)HW * BC];   // 8 MB: x transposed (HW, BC), fp16
__device__ __align__(16) int     g_cursor[SPH];            // per-sphere append cursor / count
__device__ __align__(16) unsigned long long g_sorted[(size_t)SPH * CAP]; // 64 MB buckets

// ---------------- transpose+convert x(BC, HW) fp32 -> g_xTh(HW, BC) fp16 -------
// 64x64 tiles, LDG.128 in / STG.128 out. Measured ~8us standalone.
__global__ void __launch_bounds__(256) transpose_in_k(const float* __restrict__ in) {
    __shared__ float tile[TIN][TIN + 1];    // [bc_local][hw_local]
    int tid = threadIdx.x;
    int hw0 = blockIdx.x * TIN;
    int bc0 = blockIdx.y * TIN;

    // load: 4x float4 per thread, fully coalesced rows of x(BC, HW)
    int c4 = (tid & 15) * 4;                // hw offset within tile
    int r0 = tid >> 4;                      // bc offset base (0..15)
#pragma unroll
    for (int k = 0; k < 4; k++) {
        int r = r0 + k * 16;
        float4 v = *(const float4*)&in[(size_t)(bc0 + r) * HW + hw0 + c4];
        tile[r][c4]     = v.x;
        tile[r][c4 + 1] = v.y;
        tile[r][c4 + 2] = v.z;
        tile[r][c4 + 3] = v.w;
    }
    __syncthreads();

    // store: 2x STG.128 per thread (8 fp16 channels each), 128B contiguous
    // per 8-lane group in g_xTh(HW, BC)
#pragma unroll
    for (int k = 0; k < 2; k++) {
        int i   = tid + k * 256;
        int hwl = i >> 3;                   // hw_local 0..63
        int bcg = (i & 7) * 8;              // bc_local group base
        __half hbuf[8];
#pragma unroll
        for (int j = 0; j < 8; j++)
            hbuf[j] = __float2half(tile[bcg + j][hwl]);
        *(uint4*)&g_xTh[(size_t)(hw0 + hwl) * BC + bc0 + bcg] = *(uint4*)hbuf;
    }
}

// ---------------- single-pass bucket scatter, 1 vote/thread -------------------
// Atomic-latency-bound; max thread parallelism hides ATOMG latency (R13/R14).
// Relies on g_cursor pre-zeroed (self-restored by sphere_accum_k each call).
__global__ void scatter_k(const float* __restrict__ vm, int V) {
    int v = blockIdx.x * blockDim.x + threadIdx.x;
    if (v < V) {
        int   ht = (int)vm[3 * v + 0];
        float w  =       vm[3 * v + 1];
        int   s  = (int)vm[3 * v + 2];
        int pos = atomicAdd(&g_cursor[s], 1);
        pos = pos < (CAP - 1) ? pos : (CAP - 1);   // overflow guard: never OOB
        g_sorted[((size_t)s << CAPSH) + pos] =
            ((unsigned long long)(unsigned)ht << 32) |
            (unsigned long long)__float_as_uint(w);
    }
}

// ---------------- gather-reduce + fused output transpose ----------------------
// One warp per sphere, 16 spheres per block. R15 profile: issue-bound (55%
// issue, L2 only 33%) -> this round adds (a) double-buffered vote batches so
// the next batch's seg load overlaps the current batch's 32 FMA iterations
// (closes a serial ~240cyc L2 gap per 32 votes), (b) unroll 8 + (512,2) bounds
// for deeper LDG front-batching (MLP 8/warp).
// Reads its segment count, then RE-ZEROES its own cursor entry (raceless) so
// the next graph replay starts clean. Epilogue writes DIRECTLY to out(BC, SPH).
__global__ void __launch_bounds__(512, 2) sphere_accum_k(float* __restrict__ out) {
    __shared__ float sh[SPB][BC + 1];   // +1 pad: conflict-free column reads
    int warp = threadIdx.x >> 5;
    int lane = threadIdx.x & 31;
    int s = blockIdx.x * SPB + warp;

    int n = g_cursor[s];                                   // segment count
    n = n < CAP ? n : CAP;                                 // match scatter clamp
    if (lane == 0) g_cursor[s] = 0;                        // restore for next replay
    const unsigned long long* seg = g_sorted + ((size_t)s << CAPSH);

    float4 a0 = make_float4(0.f, 0.f, 0.f, 0.f);
    float4 a1 = make_float4(0.f, 0.f, 0.f, 0.f);

    unsigned long long cur = (lane < n) ? seg[lane] : 0ull;   // batch 0
    for (int base = 0; base < n; base += 32) {
        int nx = base + 32 + lane;
        unsigned long long nxt = (nx < n) ? seg[nx] : 0ull;   // prefetch batch k+1
#pragma unroll 8
        for (int j = 0; j < 32; j++) {
            unsigned long long p = __shfl_sync(0xffffffffu, cur, j);
            int   ht = (int)(p >> 32);
            float w  = __uint_as_float((unsigned)p);
            const float4* row = (const float4*)(g_xTh + (size_t)ht * BC);
            float4 raw = __ldg(&row[lane]);          // 16B = 8 halfs = 8 channels
            const __half2* h = (const __half2*)&raw;
            float2 f0 = __half22float2(h[0]);
            float2 f1 = __half22float2(h[1]);
            float2 f2 = __half22float2(h[2]);
            float2 f3 = __half22float2(h[3]);
            a0.x = fmaf(f0.x, w, a0.x);
            a0.y = fmaf(f0.y, w, a0.y);
            a0.z = fmaf(f1.x, w, a0.z);
            a0.w = fmaf(f1.y, w, a0.w);
            a1.x = fmaf(f2.x, w, a1.x);
            a1.y = fmaf(f2.y, w, a1.y);
            a1.z = fmaf(f3.x, w, a1.z);
            a1.w = fmaf(f3.y, w, a1.w);
        }
        cur = nxt;
    }

    // stage: lane owns channels [8*lane, 8*lane+8) of sphere s
    float* r = sh[warp] + 8 * lane;
    r[0] = a0.x; r[1] = a0.y; r[2] = a0.z; r[3] = a0.w;
    r[4] = a1.x; r[5] = a1.y; r[6] = a1.z; r[7] = a1.w;
    __syncthreads();

    // fused transpose-out: out[bc][blk*SPB + s_local] = sh[s_local][bc]
    int base_s = blockIdx.x * SPB;
#pragma unroll
    for (int i = 0; i < (SPB * BC) / 512; i++) {          // 8 iterations
        int idx = threadIdx.x + i * 512;
        int s_local = idx & (SPB - 1);
        int bc      = idx >> 4;
        out[(size_t)bc * SPH + base_s + s_local] = sh[s_local][bc];
    }
}

// ---------------- launch ----------------
extern "C" void kernel_launch(void* const* d_in, const int* in_sizes, int n_in,
                              void* d_out, int out_size) {
    const float* x  = (const float*)d_in[0];   // (B, C, H, W) = (BC, HW)
    const float* vm = (const float*)d_in[1];   // (V, 3): ht, weight, sph
    float* out = (float*)d_out;                // (B, C, S) = (BC, S)
    int V = in_sizes[1] / 3;

    // 1. g_xTh(HW, BC) fp16 <- x(BC, HW) fp32
    transpose_in_k<<<dim3(HW / TIN, BC / TIN), 256>>>(x);

    // 2. single-pass bucket scatter, 1 vote/thread
    scatter_k<<<(V + 255) / 256, 256>>>(vm, V);

    // 3. gather-reduce with fused output transpose (+ cursor self-restore)
    sphere_accum_k<<<SPH / SPB, 512>>>(out);
}

// round 17
// speedup vs baseline: 1.2977x; 1.2977x over previous
#include <cuda_runtime.h>
#include <cuda_fp16.h>
#include <cstdint>

// Problem constants (HT2SPHERE: B=4, C=64, H=128, W=128, S=16384, V=1e6)
#define HW    16384     // H*W
#define BC    256       // B*C
#define SPH   16384     // sphere_size
#define CAP   512       // fixed bucket capacity per sphere (Poisson(61); P(overflow)~0)
#define CAPSH 9         // log2(CAP)
#define SPB   16        // spheres per block in sphere_accum_k (16 warps)
#define TIN   64        // transpose tile edge

// ---------------- device scratch (allocation-free rule: __device__ globals) ----
// NOTE: only referenced from device code (host-side symbol decay = ATS shadow bug).
__device__ __align__(16) __half  g_xTh[(size_t)HW * BC];   // 8 MB: x transposed (HW, BC), fp16
__device__ __align__(16) int     g_cursor[SPH];            // per-sphere append cursor / count
__device__ __align__(16) unsigned long long g_sorted[(size_t)SPH * CAP]; // 64 MB buckets

// ---------------- transpose+convert x(BC, HW) fp32 -> g_xTh(HW, BC) fp16 -------
// 64x64 tiles, LDG.128 in / STG.128 out. Measured ~8.2us standalone.
// Also zeroes g_cursor (idempotent; completes before scatter_k via stream order).
__global__ void __launch_bounds__(256) transpose_in_k(const float* __restrict__ in) {
    __shared__ float tile[TIN][TIN + 1];    // [bc_local][hw_local]
    int tid = threadIdx.x;

    if (blockIdx.y == 0) {                  // 256 blocks x 256 thr >= SPH
        int i = blockIdx.x * 256 + tid;
        if (i < SPH) g_cursor[i] = 0;
    }

    int hw0 = blockIdx.x * TIN;
    int bc0 = blockIdx.y * TIN;

    // load: 4x float4 per thread, fully coalesced rows of x(BC, HW)
    int c4 = (tid & 15) * 4;                // hw offset within tile
    int r0 = tid >> 4;                      // bc offset base (0..15)
#pragma unroll
    for (int k = 0; k < 4; k++) {
        int r = r0 + k * 16;
        float4 v = *(const float4*)&in[(size_t)(bc0 + r) * HW + hw0 + c4];
        tile[r][c4]     = v.x;
        tile[r][c4 + 1] = v.y;
        tile[r][c4 + 2] = v.z;
        tile[r][c4 + 3] = v.w;
    }
    __syncthreads();

    // store: 2x STG.128 per thread (8 fp16 channels each), 128B contiguous
    // per 8-lane group in g_xTh(HW, BC)
#pragma unroll
    for (int k = 0; k < 2; k++) {
        int i   = tid + k * 256;
        int hwl = i >> 3;                   // hw_local 0..63
        int bcg = (i & 7) * 8;              // bc_local group base
        __half hbuf[8];
#pragma unroll
        for (int j = 0; j < 8; j++)
            hbuf[j] = __float2half(tile[bcg + j][hwl]);
        *(uint4*)&g_xTh[(size_t)(hw0 + hwl) * BC + bc0 + bcg] = *(uint4*)hbuf;
    }
}

// ---------------- single-pass bucket scatter, 1 vote/thread -------------------
// Atomic-latency-bound; max thread parallelism hides ATOMG latency (R13/R14).
__global__ void scatter_k(const float* __restrict__ vm, int V) {
    int v = blockIdx.x * blockDim.x + threadIdx.x;
    if (v < V) {
        int   ht = (int)vm[3 * v + 0];
        float w  =       vm[3 * v + 1];
        int   s  = (int)vm[3 * v + 2];
        int pos = atomicAdd(&g_cursor[s], 1);
        pos = pos < (CAP - 1) ? pos : (CAP - 1);   // overflow guard: never OOB
        g_sorted[((size_t)s << CAPSH) + pos] =
            ((unsigned long long)(unsigned)ht << 32) |
            (unsigned long long)__float_as_uint(w);
    }
}

// ---------------- gather-reduce + fused output transpose ----------------------
// EXACT R14 configuration (best measured: 74.5us) + ONE change: the next vote
// batch is prefetched before the 32-iteration FMA loop, closing the serial
// ~260cyc L2 gap between batches. unroll stays 4 (R16's unroll 8 spilled regs
// and cost ~20us), launch_bounds stays (512) with no min-blocks clamp.
__global__ void __launch_bounds__(512) sphere_accum_k(float* __restrict__ out) {
    __shared__ float sh[SPB][BC + 1];   // +1 pad: conflict-free column reads
    int warp = threadIdx.x >> 5;
    int lane = threadIdx.x & 31;
    int s = blockIdx.x * SPB + warp;

    int n = g_cursor[s];                                   // segment count
    n = n < CAP ? n : CAP;                                 // match scatter clamp
    const unsigned long long* seg = g_sorted + ((size_t)s << CAPSH);

    float4 a0 = make_float4(0.f, 0.f, 0.f, 0.f);
    float4 a1 = make_float4(0.f, 0.f, 0.f, 0.f);

    unsigned long long cur = (lane < n) ? seg[lane] : 0ull;   // batch 0
    for (int base = 0; base < n; base += 32) {
        int nx = base + 32 + lane;
        unsigned long long nxt = (nx < n) ? seg[nx] : 0ull;   // prefetch batch k+1
#pragma unroll 4
        for (int j = 0; j < 32; j++) {
            unsigned long long p = __shfl_sync(0xffffffffu, cur, j);
            int   ht = (int)(p >> 32);
            float w  = __uint_as_float((unsigned)p);
            const float4* row = (const float4*)(g_xTh + (size_t)ht * BC);
            float4 raw = __ldg(&row[lane]);          // 16B = 8 halfs = 8 channels
            const __half2* h = (const __half2*)&raw;
            float2 f0 = __half22float2(h[0]);
            float2 f1 = __half22float2(h[1]);
            float2 f2 = __half22float2(h[2]);
            float2 f3 = __half22float2(h[3]);
            a0.x = fmaf(f0.x, w, a0.x);
            a0.y = fmaf(f0.y, w, a0.y);
            a0.z = fmaf(f1.x, w, a0.z);
            a0.w = fmaf(f1.y, w, a0.w);
            a1.x = fmaf(f2.x, w, a1.x);
            a1.y = fmaf(f2.y, w, a1.y);
            a1.z = fmaf(f3.x, w, a1.z);
            a1.w = fmaf(f3.y, w, a1.w);
        }
        cur = nxt;
    }

    // stage: lane owns channels [8*lane, 8*lane+8) of sphere s
    float* r = sh[warp] + 8 * lane;
    r[0] = a0.x; r[1] = a0.y; r[2] = a0.z; r[3] = a0.w;
    r[4] = a1.x; r[5] = a1.y; r[6] = a1.z; r[7] = a1.w;
    __syncthreads();

    // fused transpose-out: out[bc][blk*SPB + s_local] = sh[s_local][bc]
    int base_s = blockIdx.x * SPB;
#pragma unroll
    for (int i = 0; i < (SPB * BC) / 512; i++) {          // 8 iterations
        int idx = threadIdx.x + i * 512;
        int s_local = idx & (SPB - 1);
        int bc      = idx >> 4;
        out[(size_t)bc * SPH + base_s + s_local] = sh[s_local][bc];
    }
}

// ---------------- launch ----------------
extern "C" void kernel_launch(void* const* d_in, const int* in_sizes, int n_in,
                              void* d_out, int out_size) {
    const float* x  = (const float*)d_in[0];   // (B, C, H, W) = (BC, HW)
    const float* vm = (const float*)d_in[1];   // (V, 3): ht, weight, sph
    float* out = (float*)d_out;                // (B, C, S) = (BC, S)
    int V = in_sizes[1] / 3;

    // 1. g_xTh(HW, BC) fp16 <- x(BC, HW) fp32   (+ zero g_cursor)
    transpose_in_k<<<dim3(HW / TIN, BC / TIN), 256>>>(x);

    // 2. single-pass bucket scatter, 1 vote/thread
    scatter_k<<<(V + 255) / 256, 256>>>(vm, V);

    // 3. gather-reduce with fused output transpose
    sphere_accum_k<<<SPH / SPB, 512>>>(out);
}